// round 6
// baseline (speedup 1.0000x reference)
#include <cuda_runtime.h>
#include <cuda_fp16.h>

// Problem constants (fixed by the reference)
#define NN      100000      // nodes
#define FF      32          // feats
#define CC      16          // classes
#define EE      1600000     // edges
#define EMB_DIM 6
#define HID     9
#define DEPTH   10
#define DIFF    0.9f
#define ODIFF   0.1f        // 1 - DIFF

#define NF  (NN * FF)
#define NH4 (NN * 4)        // uint4 (8 halfs) per node row of 32 halfs

// ---------------- device scratch (no allocs allowed) ----------------
__device__ int    g_cnt[NN];
__device__ int    g_cur[NN];
__device__ int    g_rowptr[NN + 1];
__device__ int    g_col[EE];
__device__ float  g_invdeg[NN];
__device__ float  g_isd[NN];   // rsqrt(max(deg,1))
__device__ float  g_sqd[NN];   // sqrt(max(deg,1))
__device__ uint4  g_h0[NH4];   // u0 in half (row = 32 halfs = 64B)
__device__ uint4  g_ha[NH4];   // ping
__device__ uint4  g_hb[NH4];   // pong
__device__ float  g_uf[NF];    // fp32 final result of each diffuse phase

__device__ __forceinline__ uint4* hbuf(int sel) {
    return (sel == 0) ? g_h0 : (sel == 1) ? g_ha : g_hb;
}

__device__ __forceinline__ void add8(float* a, uint4 v) {
    const half2* h = reinterpret_cast<const half2*>(&v);
    float2 f0 = __half22float2(h[0]);
    float2 f1 = __half22float2(h[1]);
    float2 f2 = __half22float2(h[2]);
    float2 f3 = __half22float2(h[3]);
    a[0] += f0.x; a[1] += f0.y;
    a[2] += f1.x; a[3] += f1.y;
    a[4] += f2.x; a[5] += f2.y;
    a[6] += f3.x; a[7] += f3.y;
}

__device__ __forceinline__ void unpack8(float* a, uint4 v) {
    const half2* h = reinterpret_cast<const half2*>(&v);
    float2 f0 = __half22float2(h[0]);
    float2 f1 = __half22float2(h[1]);
    float2 f2 = __half22float2(h[2]);
    float2 f3 = __half22float2(h[3]);
    a[0] = f0.x; a[1] = f0.y;
    a[2] = f1.x; a[3] = f1.y;
    a[4] = f2.x; a[5] = f2.y;
    a[6] = f3.x; a[7] = f3.y;
}

__device__ __forceinline__ uint4 pack8(const float* a) {
    uint4 r;
    half2* h = reinterpret_cast<half2*>(&r);
    h[0] = __floats2half2_rn(a[0], a[1]);
    h[1] = __floats2half2_rn(a[2], a[3]);
    h[2] = __floats2half2_rn(a[4], a[5]);
    h[3] = __floats2half2_rn(a[6], a[7]);
    return r;
}

// gather 8 floats of x-row s (scaled by isd[s]) into acc
__device__ __forceinline__ void addx(float* a, const float* __restrict__ x,
                                     int s, int fl) {
    float is = __ldg(&g_isd[s]);
    const float4* p = reinterpret_cast<const float4*>(x + s * 32 + fl * 8);
    float4 v0 = __ldg(p);
    float4 v1 = __ldg(p + 1);
    a[0] = fmaf(is, v0.x, a[0]); a[1] = fmaf(is, v0.y, a[1]);
    a[2] = fmaf(is, v0.z, a[2]); a[3] = fmaf(is, v0.w, a[3]);
    a[4] = fmaf(is, v1.x, a[4]); a[5] = fmaf(is, v1.y, a[5]);
    a[6] = fmaf(is, v1.z, a[6]); a[7] = fmaf(is, v1.w, a[7]);
}

// ---------------- kernels ----------------

// counts dst degrees; also zeroes g_cur (used only later by k_fill)
__global__ void k_count(const int* __restrict__ edges) {
    int e = blockIdx.x * blockDim.x + threadIdx.x;
    if (e < NN) g_cur[e] = 0;
    if (e < EE) {
        int d = edges[EE + e];
        if ((unsigned)d < (unsigned)NN)
            atomicAdd(&g_cnt[d], 1);
    }
}

// single-block exclusive scan of g_cnt -> g_rowptr, plus per-node scalars
__global__ void k_scan() {
    const int T = 1024;
    int tid = threadIdx.x;
    int chunk = (NN + T - 1) / T;                 // 98
    int beg = tid * chunk;
    int end = beg + chunk; if (end > NN) end = NN;
    if (beg > NN) beg = NN;

    int sum = 0;
    for (int i = beg; i < end; i++) sum += g_cnt[i];

    __shared__ int sh[T];
    sh[tid] = sum;
    __syncthreads();
    for (int off = 1; off < T; off <<= 1) {
        int v = (tid >= off) ? sh[tid - off] : 0;
        __syncthreads();
        sh[tid] += v;
        __syncthreads();
    }
    int run = (tid == 0) ? 0 : sh[tid - 1];       // exclusive prefix
    for (int i = beg; i < end; i++) {
        g_rowptr[i] = run;
        int c = g_cnt[i];
        run += c;
        float d   = (c > 0) ? (float)c : 1.0f;
        float isd = rsqrtf(d);
        g_invdeg[i] = 1.0f / d;
        g_isd[i]    = isd;
        g_sqd[i]    = sqrtf(d);
    }
    if (tid == T - 1) g_rowptr[NN] = run;         // == EE
}

__global__ void k_fill(const int* __restrict__ edges) {
    int e = blockIdx.x * blockDim.x + threadIdx.x;
    if (e < EE) {
        int s = edges[e];
        int d = edges[EE + e];
        if ((unsigned)d < (unsigned)NN && (unsigned)s < (unsigned)NN) {
            int pos = g_rowptr[d] + atomicAdd(&g_cur[d], 1);
            g_col[pos] = s;
        }
    }
}

// One warp = 2 dst nodes (16 lanes each). Per node: 4 groups of 4 lanes;
// group g handles neighbors beg+g, beg+g+4, beg+g+8, beg+g+12 per iteration
// (4 independent idx + 4 independent value loads per lane in flight).
// Lane loads 16B of the 64B half row (uint4 = 8 halfs), fp32 accumulate.
// FIRST: input rows come from fp32 x scaled by isd[s]; also writes g_h0.
// OUT_HALF: write half row to hbuf(out_sel); else fp32 row to g_uf.
template <bool FIRST, bool OUT_HALF>
__global__ void __launch_bounds__(256) k_conv(const float* __restrict__ x,
                                              int in_sel, int out_sel) {
    const uint4* __restrict__ u_in = hbuf(in_sel);

    int warp = (blockIdx.x * blockDim.x + threadIdx.x) >> 5;
    int lane = threadIdx.x & 31;
    int hid  = lane >> 4;         // node-of-pair 0/1
    int grp  = (lane >> 2) & 3;   // neighbor group 0..3
    int fl   = lane & 3;          // 16B slot within row 0..3
    int node = warp * 2 + hid;
    if (node >= NN) return;

    int beg = g_rowptr[node];
    int end = g_rowptr[node + 1];

    float acc[8] = {0.f, 0.f, 0.f, 0.f, 0.f, 0.f, 0.f, 0.f};
    int j = beg + grp;
    if (FIRST) {
        for (; j + 12 < end; j += 16) {
            int s0 = __ldg(&g_col[j]);
            int s1 = __ldg(&g_col[j + 4]);
            int s2 = __ldg(&g_col[j + 8]);
            int s3 = __ldg(&g_col[j + 12]);
            addx(acc, x, s0, fl);
            addx(acc, x, s1, fl);
            addx(acc, x, s2, fl);
            addx(acc, x, s3, fl);
        }
        for (; j < end; j += 4)
            addx(acc, x, __ldg(&g_col[j]), fl);
    } else {
        for (; j + 12 < end; j += 16) {
            int s0 = __ldg(&g_col[j]);
            int s1 = __ldg(&g_col[j + 4]);
            int s2 = __ldg(&g_col[j + 8]);
            int s3 = __ldg(&g_col[j + 12]);
            uint4 a = __ldg(&u_in[s0 * 4 + fl]);
            uint4 b = __ldg(&u_in[s1 * 4 + fl]);
            uint4 c = __ldg(&u_in[s2 * 4 + fl]);
            uint4 d = __ldg(&u_in[s3 * 4 + fl]);
            add8(acc, a); add8(acc, b); add8(acc, c); add8(acc, d);
        }
        for (; j < end; j += 4)
            add8(acc, __ldg(&u_in[__ldg(&g_col[j]) * 4 + fl]));
    }

    // combine 4 group partials within each 16-lane half (xor bits 2,3 only)
    #pragma unroll
    for (int off = 4; off <= 8; off <<= 1) {
        #pragma unroll
        for (int k = 0; k < 8; k++)
            acc[k] += __shfl_xor_sync(0xffffffffu, acc[k], off);
    }

    if (grp == 0) {
        float w = DIFF * __ldg(&g_invdeg[node]);
        float h0[8];
        if (FIRST) {
            float is = __ldg(&g_isd[node]);
            const float4* p = reinterpret_cast<const float4*>(x + node * 32 + fl * 8);
            float4 v0 = __ldg(p);
            float4 v1 = __ldg(p + 1);
            h0[0] = is * v0.x; h0[1] = is * v0.y; h0[2] = is * v0.z; h0[3] = is * v0.w;
            h0[4] = is * v1.x; h0[5] = is * v1.y; h0[6] = is * v1.z; h0[7] = is * v1.w;
            g_h0[node * 4 + fl] = pack8(h0);   // persist u0 for later steps
        } else {
            unpack8(h0, __ldg(&g_h0[node * 4 + fl]));
        }
        float r[8];
        #pragma unroll
        for (int k = 0; k < 8; k++)
            r[k] = fmaf(w, acc[k], ODIFF * h0[k]);
        if (OUT_HALF) {
            hbuf(out_sel)[node * 4 + fl] = pack8(r);
        } else {
            float4* o = reinterpret_cast<float4*>(g_uf);
            o[node * 8 + fl * 2 + 0] = make_float4(r[0], r[1], r[2], r[3]);
            o[node * 8 + fl * 2 + 1] = make_float4(r[4], r[5], r[6], r[7]);
        }
    }
}

// per-(node,feature) MLP elementwise, rescaled in/out of u-space.
// Reads g_uf (fp32), writes new u0 (half) into g_h0. Two feats per thread.
__global__ void k_mlp(const float* __restrict__ emb,
                      const float* __restrict__ W1,
                      const float* __restrict__ b1,
                      const float* __restrict__ W2,
                      const float* __restrict__ b2) {
    __shared__ float sA[HID];           // W1 row 0
    __shared__ float sW2[HID];
    __shared__ float sC[FF][HID];       // b1[j] + sum_d emb[f,d]*W1[1+d,j]
    __shared__ float sB2;

    for (int t = threadIdx.x; t < FF * HID; t += blockDim.x) {
        int f = t / HID, j = t % HID;
        float c = b1[j];
        #pragma unroll
        for (int d = 0; d < EMB_DIM; d++)
            c += emb[f * EMB_DIM + d] * W1[(1 + d) * HID + j];
        sC[f][j] = c;
    }
    if (threadIdx.x < HID) {
        sA[threadIdx.x]  = W1[threadIdx.x];      // row 0
        sW2[threadIdx.x] = W2[threadIdx.x];
    }
    if (threadIdx.x == 0) sB2 = b2[0];
    __syncthreads();

    int idx2 = blockIdx.x * blockDim.x + threadIdx.x;   // half2 index
    if (idx2 >= NF / 2) return;
    int n  = idx2 >> 4;
    int f0 = (idx2 & 15) * 2;
    float sq  = g_sqd[n];
    float isd = g_isd[n];
    float2 tv = reinterpret_cast<const float2*>(g_uf)[idx2];
    float t0 = tv.x * sq, t1 = tv.y * sq;
    float r0 = sB2, r1 = sB2;
    #pragma unroll
    for (int j = 0; j < HID; j++) {
        float h0 = fmaf(sA[j], t0, sC[f0][j]);
        float h1 = fmaf(sA[j], t1, sC[f0 + 1][j]);
        r0 = fmaf(sW2[j], fmaxf(h0, 0.0f), r0);
        r1 = fmaf(sW2[j], fmaxf(h1, 0.0f), r1);
    }
    reinterpret_cast<half2*>(g_h0)[idx2] = __floats2half2_rn(r0 * isd, r1 * isd);
}

// out[n,c] = bout[c] + sum_k (g_uf[n,k]*sqd[n]) * Wout[k,c]
__global__ void k_out(const float* __restrict__ Wout,
                      const float* __restrict__ bout,
                      float* __restrict__ out) {
    __shared__ float sW[FF * CC];
    __shared__ float sb[CC];
    for (int t = threadIdx.x; t < FF * CC; t += blockDim.x) sW[t] = Wout[t];
    if (threadIdx.x < CC) sb[threadIdx.x] = bout[threadIdx.x];
    __syncthreads();

    int tid = blockIdx.x * blockDim.x + threadIdx.x;
    if (tid >= NN * CC) return;
    int n = tid >> 4;
    int c = tid & 15;
    float sd = g_sqd[n];
    float acc = sb[c];
    #pragma unroll
    for (int k = 0; k < FF; k++)
        acc = fmaf(g_uf[n * 32 + k] * sd, sW[k * CC + c], acc);
    out[tid] = acc;
}

// ---------------- launch ----------------

extern "C" void kernel_launch(void* const* d_in, const int* in_sizes, int n_in,
                              void* d_out, int out_size) {
    const float* x     = (const float*)d_in[0];
    const int*   edges = (const int*)d_in[1];       // int32 per harness dtype contract
    const float* emb   = (const float*)d_in[2];
    const float* W1    = (const float*)d_in[3];
    const float* b1    = (const float*)d_in[4];
    const float* W2    = (const float*)d_in[5];
    const float* b2    = (const float*)d_in[6];
    const float* Wout  = (const float*)d_in[7];
    const float* bout  = (const float*)d_in[8];
    float* out = (float*)d_out;

    const int TB = 256;
    int gE  = (EE + TB - 1) / TB;
    int gH2 = (NF / 2 + TB - 1) / TB;            // half2-element grid
    int gC  = ((NN / 2) * 32 + TB - 1) / TB;     // 2-nodes-per-warp conv grid
    int gNC = (NN * CC + TB - 1) / TB;

    // CSR build (g_cnt via async memset; g_cur zeroed inside k_count)
    void* cntp = nullptr;
    cudaGetSymbolAddress(&cntp, g_cnt);
    cudaMemsetAsync(cntp, 0, NN * sizeof(int));
    k_count<<<gE, TB>>>(edges);
    k_scan<<<1, 1024>>>();
    k_fill<<<gE, TB>>>(edges);

    // phase 1: step 1 reads x (fp32), writes ha(1) + persists u0 into g_h0
    k_conv<true, true><<<gC, TB>>>(x, 0, 1);
    for (int i = 2; i < DEPTH; i++) {
        int in_sel  = (i & 1) ? 2 : 1;
        int out_sel = (i & 1) ? 1 : 2;
        k_conv<false, true><<<gC, TB>>>(x, in_sel, out_sel);
    }
    k_conv<false, false><<<gC, TB>>>(x, 1, 0);   // step 10 -> fp32 g_uf

    // per-element MLP (reads g_uf, writes new half u0 into g_h0)
    k_mlp<<<gH2, TB>>>(emb, W1, b1, W2, b2);

    // phase 2: standard steps from g_h0
    k_conv<false, true><<<gC, TB>>>(x, 0, 1);
    for (int i = 2; i < DEPTH; i++) {
        int in_sel  = (i & 1) ? 2 : 1;
        int out_sel = (i & 1) ? 1 : 2;
        k_conv<false, true><<<gC, TB>>>(x, in_sel, out_sel);
    }
    k_conv<false, false><<<gC, TB>>>(x, 1, 0);   // step 10 -> fp32 g_uf

    // output GEMM
    k_out<<<gNC, TB>>>(Wout, bout, out);
}